// round 9
// baseline (speedup 1.0000x reference)
#include <cuda_runtime.h>
#include <math.h>
#include <stdint.h>

#define TT 1024
#define HH 2048
#define II 1024
#define EE 32

// ---------------- scratch (device globals; no allocs) ----------------
__device__ __align__(256) int   g_top2_idx[TT * 2];
__device__ __align__(256) float g_top2_w[TT * 2];
__device__ __align__(256) int   g_cnt[EE];
__device__ __align__(256) int   g_toklist[EE * TT];          // packed (t<<1)|slot
__device__ __align__(256) float g_act[TT * 2 * II];          // 8 MB
__device__ __align__(256) float g_partial[2 * TT * HH];      // 16 MB

// ---------------- tf32 mma.sync helpers ----------------
__device__ __forceinline__ uint32_t f2tf(float f) {
    uint32_t r; asm("cvt.rna.tf32.f32 %0, %1;" : "=r"(r) : "f"(f)); return r;
}
__device__ __forceinline__ void mma1688(float* d, const uint32_t* a, const uint32_t* b) {
    asm volatile(
        "mma.sync.aligned.m16n8k8.row.col.f32.tf32.tf32.f32 "
        "{%0,%1,%2,%3}, {%4,%5,%6,%7}, {%8,%9}, {%0,%1,%2,%3};"
        : "+f"(d[0]), "+f"(d[1]), "+f"(d[2]), "+f"(d[3])
        : "r"(a[0]), "r"(a[1]), "r"(a[2]), "r"(a[3]), "r"(b[0]), "r"(b[1]));
}
__device__ __forceinline__ uint4 cvt4(float4 v) {
    uint4 o; o.x = f2tf(v.x); o.y = f2tf(v.y); o.z = f2tf(v.z); o.w = f2tf(v.w);
    return o;
}

#define LDW 36   // 32 k + 4 pad: frag LDS bank = 4g+tig, conflict-free

// ---------------- 1. router ----------------
__global__ __launch_bounds__(256) void router_k(const float* __restrict__ x,
                                                const float* __restrict__ gw) {
    __shared__ float xs[HH];
    __shared__ float lg[EE];
    int t = blockIdx.x;
    const float* xr = x + (size_t)t * HH;
    for (int i = threadIdx.x; i < HH; i += 256) xs[i] = xr[i];
    __syncthreads();
    int w = threadIdx.x >> 5, lane = threadIdx.x & 31;
    for (int e = w; e < EE; e += 8) {
        const float* g = gw + (size_t)e * HH;
        float s = 0.f;
        for (int h = lane; h < HH; h += 32) s += xs[h] * g[h];
        #pragma unroll
        for (int o = 16; o; o >>= 1) s += __shfl_xor_sync(0xffffffffu, s, o);
        if (!lane) lg[e] = s;
    }
    __syncthreads();
    if (threadIdx.x == 0) {
        float m1 = -1e30f, m2 = -1e30f; int i1 = 0, i2 = 1;
        for (int e = 0; e < EE; e++) {
            float v = lg[e];
            if (v > m1)      { m2 = m1; i2 = i1; m1 = v; i1 = e; }
            else if (v > m2) { m2 = v; i2 = e; }
        }
        float q = expf(m2 - m1);
        float w1 = 1.f / (1.f + q);
        g_top2_idx[2 * t] = i1;  g_top2_idx[2 * t + 1] = i2;
        g_top2_w[2 * t] = w1;    g_top2_w[2 * t + 1] = 1.f - w1;
    }
}

// ---------------- 2. per-expert token lists ----------------
__global__ void zero_k() { if (threadIdx.x < EE) g_cnt[threadIdx.x] = 0; }

__global__ void scatter_k() {
    int t = blockIdx.x * blockDim.x + threadIdx.x;
    if (t >= TT) return;
    #pragma unroll
    for (int s = 0; s < 2; s++) {
        int e = g_top2_idx[2 * t + s];
        int pos = atomicAdd(&g_cnt[e], 1);
        g_toklist[e * TT + pos] = (t << 1) | s;
    }
}

// ---------------- 3. gate+up grouped GEMM: 128tok x 64i x BK32 ----------------
// block 512 = 16 warps (4 m x 4 n), warp tile 32x16 per matrix, double-buffered.
__global__ __launch_bounds__(512) void gateup_mma(const float* __restrict__ x,
                                                  const float* __restrict__ gw,
                                                  const float* __restrict__ uw) {
    int e = blockIdx.x;
    int cnt = g_cnt[e];
    int m0 = blockIdx.z << 7;
    if (m0 >= cnt) return;
    int i0 = blockIdx.y << 6;

    extern __shared__ uint32_t dsm[];
    const int ASZ = 128 * LDW, BSZ = 64 * LDW, BUF = ASZ + 2 * BSZ;

    __shared__ int   stok[128];
    __shared__ float swt[128];

    int tid = threadIdx.x, wid = tid >> 5, lane = tid & 31;
    int g = lane >> 2, tig = lane & 3;
    int m_base = (wid >> 2) * 32;        // 0..96
    int n_base = (wid & 3) * 16;         // 0..48

    if (tid < 128) {
        int m = m0 + tid;
        if (m < cnt) { int p = g_toklist[e * TT + m]; stok[tid] = p; swt[tid] = g_top2_w[p]; }
        else         { stok[tid] = g_toklist[e * TT]; swt[tid] = 0.f; }
    }
    __syncthreads();

    // staging: A 2 float4/thread (128 rows x 8 chunks), G/U 1 float4/thread
    const float* ap[2]; uint32_t soa[2];
    #pragma unroll
    for (int c = 0; c < 2; c++) {
        int f = c * 512 + tid, row = f >> 3, q = f & 7;
        ap[c]  = x + (size_t)(stok[row] >> 1) * HH + q * 4;
        soa[c] = row * LDW + q * 4;
    }
    const float* gp; const float* up_; uint32_t sob;
    {
        int row = tid >> 3, q = tid & 7;
        gp  = gw + ((size_t)e * II + i0 + row) * HH + q * 4;
        up_ = uw + ((size_t)e * II + i0 + row) * HH + q * 4;
        sob = row * LDW + q * 4;
    }

    float accG[2][2][4], accU[2][2][4];
    #pragma unroll
    for (int mt = 0; mt < 2; mt++)
        #pragma unroll
        for (int nt = 0; nt < 2; nt++)
            #pragma unroll
            for (int j = 0; j < 4; j++) { accG[mt][nt][j] = 0.f; accU[mt][nt][j] = 0.f; }

    const int NIT = HH / 32;
    float4 av[2], gv, uv;
    av[0] = *(const float4*)(ap[0]);
    av[1] = *(const float4*)(ap[1]);
    gv = *(const float4*)(gp);
    uv = *(const float4*)(up_);

    for (int it = 0; it < NIT; it++) {
        uint32_t* B = dsm + (it & 1) * BUF;
        *(uint4*)&B[soa[0]] = cvt4(av[0]);
        *(uint4*)&B[soa[1]] = cvt4(av[1]);
        *(uint4*)&B[ASZ + sob]       = cvt4(gv);
        *(uint4*)&B[ASZ + BSZ + sob] = cvt4(uv);
        __syncthreads();
        if (it + 1 < NIT) {                  // prefetch next tile while MMA runs
            int k0 = (it + 1) * 32;
            av[0] = *(const float4*)(ap[0] + k0);
            av[1] = *(const float4*)(ap[1] + k0);
            gv = *(const float4*)(gp + k0);
            uv = *(const float4*)(up_ + k0);
        }
        #pragma unroll
        for (int ks = 0; ks < 4; ks++) {
            int kk = ks * 8;
            uint32_t af[2][4];
            #pragma unroll
            for (int mt = 0; mt < 2; mt++) {
                int rb = m_base + mt * 16 + g;
                af[mt][0] = B[rb * LDW + kk + tig];
                af[mt][1] = B[(rb + 8) * LDW + kk + tig];
                af[mt][2] = B[rb * LDW + kk + tig + 4];
                af[mt][3] = B[(rb + 8) * LDW + kk + tig + 4];
            }
            #pragma unroll
            for (int nt = 0; nt < 2; nt++) {
                int cb = (n_base + nt * 8 + g) * LDW + kk + tig;
                uint32_t bg[2] = { B[ASZ + cb], B[ASZ + cb + 4] };
                uint32_t bu[2] = { B[ASZ + BSZ + cb], B[ASZ + BSZ + cb + 4] };
                #pragma unroll
                for (int mt = 0; mt < 2; mt++) {
                    mma1688(accG[mt][nt], af[mt], bg);
                    mma1688(accU[mt][nt], af[mt], bu);
                }
            }
        }
    }

    // fused SwiGLU + routing-weight epilogue
    #pragma unroll
    for (int mt = 0; mt < 2; mt++) {
        int r0 = m_base + mt * 16 + g;
        #pragma unroll
        for (int half = 0; half < 2; half++) {
            int rr = r0 + half * 8;
            if (m0 + rr < cnt) {
                int p = stok[rr]; float wgt = swt[rr];
                float* orow = g_act + (size_t)p * II + i0;
                #pragma unroll
                for (int nt = 0; nt < 2; nt++) {
                    float g0 = accG[mt][nt][half * 2], g1 = accG[mt][nt][half * 2 + 1];
                    float u0 = accU[mt][nt][half * 2], u1 = accU[mt][nt][half * 2 + 1];
                    float2 o;
                    o.x = (g0 / (1.f + expf(-g0))) * u0 * wgt;
                    o.y = (g1 / (1.f + expf(-g1))) * u1 * wgt;
                    *(float2*)(orow + n_base + nt * 8 + tig * 2) = o;
                }
            }
        }
    }
}

// ---------------- 4. down grouped GEMM: 128tok x 64h x BK32 ----------------
// block 512 = 16 warps (4 m x 4 n), warp tile 32x16, double-buffered; K = II.
__global__ __launch_bounds__(512) void down_mma(const float* __restrict__ dw) {
    int e = blockIdx.x;
    int cnt = g_cnt[e];
    int m0 = blockIdx.z << 7;
    if (m0 >= cnt) return;
    int h0 = blockIdx.y << 6;

    extern __shared__ uint32_t dsm[];
    const int ASZ = 128 * LDW, BSZ = 64 * LDW, BUF = ASZ + BSZ;

    __shared__ int stok[128];

    int tid = threadIdx.x, wid = tid >> 5, lane = tid & 31;
    int g = lane >> 2, tig = lane & 3;
    int m_base = (wid >> 2) * 32;
    int n_base = (wid & 3) * 16;

    if (tid < 128) {
        int m = m0 + tid;
        stok[tid] = (m < cnt) ? g_toklist[e * TT + m] : g_toklist[e * TT];
    }
    __syncthreads();

    const float* ap[2]; uint32_t soa[2];
    #pragma unroll
    for (int c = 0; c < 2; c++) {
        int f = c * 512 + tid, row = f >> 3, q = f & 7;
        ap[c]  = g_act + (size_t)stok[row] * II + q * 4;
        soa[c] = row * LDW + q * 4;
    }
    const float* bp; uint32_t sob;
    {
        int row = tid >> 3, q = tid & 7;
        bp  = dw + ((size_t)e * HH + h0 + row) * II + q * 4;
        sob = row * LDW + q * 4;
    }

    float acc[2][2][4];
    #pragma unroll
    for (int mt = 0; mt < 2; mt++)
        #pragma unroll
        for (int nt = 0; nt < 2; nt++)
            #pragma unroll
            for (int j = 0; j < 4; j++) acc[mt][nt][j] = 0.f;

    const int NIT = II / 32;
    float4 av[2], bv;
    av[0] = *(const float4*)(ap[0]);
    av[1] = *(const float4*)(ap[1]);
    bv = *(const float4*)(bp);

    for (int it = 0; it < NIT; it++) {
        uint32_t* B = dsm + (it & 1) * BUF;
        *(uint4*)&B[soa[0]] = cvt4(av[0]);
        *(uint4*)&B[soa[1]] = cvt4(av[1]);
        *(uint4*)&B[ASZ + sob] = cvt4(bv);
        __syncthreads();
        if (it + 1 < NIT) {
            int k0 = (it + 1) * 32;
            av[0] = *(const float4*)(ap[0] + k0);
            av[1] = *(const float4*)(ap[1] + k0);
            bv = *(const float4*)(bp + k0);
        }
        #pragma unroll
        for (int ks = 0; ks < 4; ks++) {
            int kk = ks * 8;
            uint32_t af[2][4];
            #pragma unroll
            for (int mt = 0; mt < 2; mt++) {
                int rb = m_base + mt * 16 + g;
                af[mt][0] = B[rb * LDW + kk + tig];
                af[mt][1] = B[(rb + 8) * LDW + kk + tig];
                af[mt][2] = B[rb * LDW + kk + tig + 4];
                af[mt][3] = B[(rb + 8) * LDW + kk + tig + 4];
            }
            #pragma unroll
            for (int nt = 0; nt < 2; nt++) {
                int cb = (n_base + nt * 8 + g) * LDW + kk + tig;
                uint32_t bb[2] = { B[ASZ + cb], B[ASZ + cb + 4] };
                #pragma unroll
                for (int mt = 0; mt < 2; mt++) mma1688(acc[mt][nt], af[mt], bb);
            }
        }
    }

    #pragma unroll
    for (int mt = 0; mt < 2; mt++) {
        int r0 = m_base + mt * 16 + g;
        #pragma unroll
        for (int half = 0; half < 2; half++) {
            int rr = r0 + half * 8;
            if (m0 + rr < cnt) {
                int p = stok[rr];
                int t = p >> 1, s = p & 1;
                float* orow = g_partial + (size_t)s * TT * HH + (size_t)t * HH + h0;
                #pragma unroll
                for (int nt = 0; nt < 2; nt++) {
                    float2 o;
                    o.x = acc[mt][nt][half * 2];
                    o.y = acc[mt][nt][half * 2 + 1];
                    *(float2*)(orow + n_base + nt * 8 + tig * 2) = o;
                }
            }
        }
    }
}

// ---------------- 5. combine slot partials ----------------
__global__ void combine_k(float* __restrict__ out) {
    int i = blockIdx.x * 256 + threadIdx.x;
    if (i < TT * HH) out[i] = g_partial[i] + g_partial[TT * HH + i];
}

// ---------------- launch ----------------
extern "C" void kernel_launch(void* const* d_in, const int* in_sizes, int n_in,
                              void* d_out, int out_size) {
    const float* x      = (const float*)d_in[0];
    const float* gate_w = (const float*)d_in[1];
    const float* gpw    = (const float*)d_in[2];
    const float* upw    = (const float*)d_in[3];
    const float* dpw    = (const float*)d_in[4];
    float* out = (float*)d_out;

    const int GU_SMEM = 2 * (128 + 64 + 64) * LDW * 4;   // 73728 B
    const int DN_SMEM = 2 * (128 + 64) * LDW * 4;        // 55296 B
    cudaFuncSetAttribute(gateup_mma, cudaFuncAttributeMaxDynamicSharedMemorySize, GU_SMEM);
    cudaFuncSetAttribute(down_mma,   cudaFuncAttributeMaxDynamicSharedMemorySize, DN_SMEM);

    router_k<<<TT, 256>>>(x, gate_w);
    zero_k<<<1, 32>>>();
    scatter_k<<<(TT + 255) / 256, 256>>>();
    gateup_mma<<<dim3(EE, II / 64, TT / 128), 512, GU_SMEM>>>(x, gpw, upw);
    down_mma<<<dim3(EE, HH / 64, TT / 128), 512, DN_SMEM>>>(dpw);
    combine_k<<<(TT * HH + 255) / 256, 256>>>(out);
}